// round 1
// baseline (speedup 1.0000x reference)
#include <cuda_runtime.h>
#include <math.h>

#define Nn 100000
#define Ee 1600000
#define Ff 256
#define Hh 64

// ---- device scratch (static: no allocation allowed) ----
__device__ float g_h[(size_t)Nn * Hh];   // node features (layer input)
__device__ float g_q[(size_t)Nn * Hh];
__device__ float g_k[(size_t)Nn * Hh];
__device__ float g_v[(size_t)Nn * Hh];
__device__ float g_o[(size_t)Nn * Hh];   // layer aggregation output
__device__ float g_e[(size_t)Ee];        // per-edge alpha, then exp(alpha-m)
__device__ float g_m[Nn];                // per-node segment max
__device__ float g_d[Nn];                // per-node denom

__device__ __forceinline__ float gelu_exact(float v) {
    return 0.5f * v * (1.0f + erff(v * 0.70710678118654752440f));
}

// ============================================================
// proj: g_h = gelu(x @ W_proj + b)   [100000,256]x[256,64]
// blockDim 256, 32 rows/block, thread = (col j, rowgroup rg), 8 rows/thread
// smem: W [256*64] + x rows [32*256] = 96KB dynamic
// ============================================================
__global__ void proj_kernel(const float* __restrict__ x,
                            const float* __restrict__ W,
                            const float* __restrict__ b) {
    extern __shared__ float sm[];
    float* Ws = sm;              // [k][j], 256*64
    float* xs = sm + 256 * 64;   // [r][k], 32*256
    int tid = threadIdx.x;

    for (int i = tid; i < 256 * 64; i += 256) Ws[i] = W[i];
    size_t row0 = (size_t)blockIdx.x * 32;
    const float* xrow = x + row0 * 256;
    for (int i = tid; i < 32 * 256; i += 256) xs[i] = xrow[i];
    __syncthreads();

    int j = tid & 63;
    int rg = tid >> 6;            // 0..3
    float acc[8];
#pragma unroll
    for (int s = 0; s < 8; s++) acc[s] = 0.0f;

    const float4* xs4 = (const float4*)xs;
    for (int k4 = 0; k4 < 64; k4++) {
        float w0 = Ws[(4 * k4 + 0) * 64 + j];
        float w1 = Ws[(4 * k4 + 1) * 64 + j];
        float w2 = Ws[(4 * k4 + 2) * 64 + j];
        float w3 = Ws[(4 * k4 + 3) * 64 + j];
#pragma unroll
        for (int s = 0; s < 8; s++) {
            float4 xv = xs4[(rg * 8 + s) * 64 + k4];   // broadcast within warp
            acc[s] += xv.x * w0 + xv.y * w1 + xv.z * w2 + xv.w * w3;
        }
    }
    float bb = b[j];
#pragma unroll
    for (int s = 0; s < 8; s++) {
        size_t r = row0 + rg * 8 + s;
        g_h[r * 64 + j] = gelu_exact(acc[s] + bb);
    }
}

// ============================================================
// qkv: g_q/g_k/g_v = g_h @ {Wq,Wk,Wv}   [100000,64]x[64,64] x3
// blockDim 192 (thread = one of 192 output cols), 16 rows/block
// smem: Wqkv [64*192] + h rows [16*64] = 52KB dynamic
// ============================================================
__global__ void qkv_kernel(const float* __restrict__ Wq,
                           const float* __restrict__ Wk,
                           const float* __restrict__ Wv) {
    extern __shared__ float sm[];
    float* Ws = sm;               // [k][c], 64*192 (q|k|v concat on cols)
    float* hs = sm + 64 * 192;    // [r][k], 16*64
    int tid = threadIdx.x;        // 0..191

    for (int i = tid; i < 64 * 64; i += 192) {
        int k = i >> 6, c = i & 63;
        Ws[k * 192 + c]       = Wq[i];
        Ws[k * 192 + 64 + c]  = Wk[i];
        Ws[k * 192 + 128 + c] = Wv[i];
    }
    size_t row0 = (size_t)blockIdx.x * 16;
    for (int i = tid; i < 16 * 64; i += 192) hs[i] = g_h[row0 * 64 + i];
    __syncthreads();

    int c = tid;
    float acc[16];
#pragma unroll
    for (int r = 0; r < 16; r++) acc[r] = 0.0f;

    const float4* hs4 = (const float4*)hs;
    for (int k4 = 0; k4 < 16; k4++) {
        float w0 = Ws[(4 * k4 + 0) * 192 + c];
        float w1 = Ws[(4 * k4 + 1) * 192 + c];
        float w2 = Ws[(4 * k4 + 2) * 192 + c];
        float w3 = Ws[(4 * k4 + 3) * 192 + c];
#pragma unroll
        for (int r = 0; r < 16; r++) {
            float4 hv = hs4[r * 16 + k4];              // broadcast
            acc[r] += hv.x * w0 + hv.y * w1 + hv.z * w2 + hv.w * w3;
        }
    }
    float* outp;
    int cc;
    if (c < 64)       { outp = g_q; cc = c; }
    else if (c < 128) { outp = g_k; cc = c - 64; }
    else              { outp = g_v; cc = c - 128; }
#pragma unroll
    for (int r = 0; r < 16; r++) outp[(row0 + r) * 64 + cc] = acc[r];
}

// ============================================================
// init kernels
// ============================================================
__global__ void init_md_kernel() {
    int i = blockIdx.x * blockDim.x + threadIdx.x;
    if (i < Nn) { g_m[i] = 0.0f; g_d[i] = 0.0f; }
}
__global__ void zero_o_kernel() {
    int i = blockIdx.x * blockDim.x + threadIdx.x;
    g_o[i] = 0.0f;   // grid sized exactly Nn*Hh/256
}

// ============================================================
// scores: warp per edge. alpha = relu(dot(q[dst],k[src])/8)
// segment max via atomicMax on uint bits (alpha >= 0)
// ============================================================
__global__ void scores_kernel(const int* __restrict__ src,
                              const int* __restrict__ dst) {
    int gw = (blockIdx.x * blockDim.x + threadIdx.x) >> 5;
    int lane = threadIdx.x & 31;
    int s = __ldg(src + gw);
    int d = __ldg(dst + gw);
    const float* qp = g_q + (size_t)d * 64;
    const float* kp = g_k + (size_t)s * 64;
    float acc = qp[lane] * kp[lane] + qp[lane + 32] * kp[lane + 32];
#pragma unroll
    for (int off = 16; off > 0; off >>= 1)
        acc += __shfl_xor_sync(0xFFFFFFFFu, acc, off);
    if (lane == 0) {
        float a = fmaxf(acc * 0.125f, 0.0f);
        g_e[gw] = a;
        atomicMax((unsigned int*)(g_m + d), __float_as_uint(a));
    }
}

// ============================================================
// exp + denom: thread per edge
// ============================================================
__global__ void expdenom_kernel(const int* __restrict__ dst) {
    int i = blockIdx.x * blockDim.x + threadIdx.x;
    int d = __ldg(dst + i);
    float e = expf(g_e[i] - g_m[d]);
    g_e[i] = e;
    atomicAdd(g_d + d, e);
}

// ============================================================
// scatter: warp per edge. a = e/(denom+eps); attn out; out[dst]+=a*v[src]
// ============================================================
__global__ void scatter_kernel(const int* __restrict__ src,
                               const int* __restrict__ dst,
                               float* __restrict__ attn_out) {
    int gw = (blockIdx.x * blockDim.x + threadIdx.x) >> 5;
    int lane = threadIdx.x & 31;
    int s = __ldg(src + gw);
    int d = __ldg(dst + gw);
    float a = g_e[gw] / (g_d[d] + 1e-16f);
    if (lane == 0) attn_out[gw] = a;
    const float* vp = g_v + (size_t)s * 64;
    float* op = g_o + (size_t)d * 64;
    atomicAdd(op + lane,      vp[lane] * a);
    atomicAdd(op + lane + 32, vp[lane + 32] * a);
}

// ============================================================
// gelu: g_h = gelu(g_o)   (between layers)
// ============================================================
__global__ void gelu_kernel() {
    int i = blockIdx.x * blockDim.x + threadIdx.x;
    g_h[i] = gelu_exact(g_o[i]);   // grid sized exactly Nn*Hh/256
}

// ============================================================
// signals: out[i] = dot(g_o[i,:], W_sig) + b_sig
// ============================================================
__global__ void signal_kernel(const float* __restrict__ Wsig,
                              const float* __restrict__ bsig,
                              float* __restrict__ out) {
    int i = blockIdx.x * blockDim.x + threadIdx.x;
    if (i >= Nn) return;
    const float4* hp = (const float4*)(g_o + (size_t)i * 64);
    float acc = 0.0f;
#pragma unroll
    for (int t = 0; t < 16; t++) {
        float4 h4 = hp[t];
        float4 w4 = __ldg(((const float4*)Wsig) + t);
        acc += h4.x * w4.x + h4.y * w4.y + h4.z * w4.z + h4.w * w4.w;
    }
    out[i] = acc + __ldg(bsig);
}

// ============================================================
// host launcher
// ============================================================
extern "C" void kernel_launch(void* const* d_in, const int* in_sizes, int n_in,
                              void* d_out, int out_size) {
    const float* x    = (const float*)d_in[0];
    const int*   ei   = (const int*)d_in[1];
    const int*   src  = ei;          // edge_index[0]
    const int*   dst  = ei + Ee;     // edge_index[1]
    const float* Wp   = (const float*)d_in[2];
    const float* bp   = (const float*)d_in[3];
    const float* Wq1  = (const float*)d_in[4];
    const float* Wk1  = (const float*)d_in[5];
    const float* Wv1  = (const float*)d_in[6];
    const float* Wq2  = (const float*)d_in[7];
    const float* Wk2  = (const float*)d_in[8];
    const float* Wv2  = (const float*)d_in[9];
    const float* Wsig = (const float*)d_in[10];
    const float* bsig = (const float*)d_in[11];

    float* out     = (float*)d_out;
    float* signals = out;            // [Nn]
    float* attn1   = out + Nn;       // [Ee]
    float* attn2   = out + Nn + Ee;  // [Ee]

    const int PROJ_SMEM = (256 * 64 + 32 * 256) * 4;   // 96 KB
    const int QKV_SMEM  = (64 * 192 + 16 * 64) * 4;    // 52 KB
    cudaFuncSetAttribute(proj_kernel, cudaFuncAttributeMaxDynamicSharedMemorySize, PROJ_SMEM);
    cudaFuncSetAttribute(qkv_kernel,  cudaFuncAttributeMaxDynamicSharedMemorySize, QKV_SMEM);

    // ---- proj + gelu ----
    proj_kernel<<<Nn / 32, 256, PROJ_SMEM>>>(x, Wp, bp);

    // ---- layer 1 ----
    qkv_kernel<<<Nn / 16, 192, QKV_SMEM>>>(Wq1, Wk1, Wv1);
    init_md_kernel<<<(Nn + 255) / 256, 256>>>();
    zero_o_kernel<<<(Nn * Hh) / 256, 256>>>();
    scores_kernel<<<Ee / 8, 256>>>(src, dst);
    expdenom_kernel<<<Ee / 256, 256>>>(dst);
    scatter_kernel<<<Ee / 8, 256>>>(src, dst, attn1);
    gelu_kernel<<<(Nn * Hh) / 256, 256>>>();

    // ---- layer 2 ----
    qkv_kernel<<<Nn / 16, 192, QKV_SMEM>>>(Wq2, Wk2, Wv2);
    init_md_kernel<<<(Nn + 255) / 256, 256>>>();
    zero_o_kernel<<<(Nn * Hh) / 256, 256>>>();
    scores_kernel<<<Ee / 8, 256>>>(src, dst);
    expdenom_kernel<<<Ee / 256, 256>>>(dst);
    scatter_kernel<<<Ee / 8, 256>>>(src, dst, attn2);

    // ---- signals ----
    signal_kernel<<<(Nn + 255) / 256, 256>>>(Wsig, bsig, signals);
}

// round 2
// speedup vs baseline: 1.6583x; 1.6583x over previous
#include <cuda_runtime.h>
#include <math.h>

#define Nn 100000
#define Ee 1600000
#define Ff 256
#define Hh 64
#define NB_SCAN 98   // ceil(Nn/1024)

// ---- device scratch (static: no allocation allowed) ----
__device__ float g_h[(size_t)Nn * Hh];   // node features (layer input)
__device__ float g_q[(size_t)Nn * Hh];
__device__ float g_k[(size_t)Nn * Hh];
__device__ float g_v[(size_t)Nn * Hh];
__device__ float g_e[(size_t)Ee];        // per-edge alpha, then exp(alpha-m)
__device__ int   g_cnt[Nn];              // per-dst degree
__device__ int   g_off[Nn];              // CSR exclusive offsets
__device__ int   g_cur[Nn];              // fill cursors
__device__ int   g_csrc[Ee];             // CSR: source node per slot
__device__ int   g_ceid[Ee];             // CSR: original edge id per slot
__device__ int   g_bsum[128];
__device__ int   g_bpre[128];

__device__ __forceinline__ float gelu_exact(float v) {
    return 0.5f * v * (1.0f + erff(v * 0.70710678118654752440f));
}

// ============================================================
// proj: g_h = gelu(x @ W_proj + b)   [100000,256]x[256,64]
// ============================================================
__global__ void proj_kernel(const float* __restrict__ x,
                            const float* __restrict__ W,
                            const float* __restrict__ b) {
    extern __shared__ float sm[];
    float* Ws = sm;              // [k][j], 256*64
    float* xs = sm + 256 * 64;   // [r][k], 32*256
    int tid = threadIdx.x;

    for (int i = tid; i < 256 * 64; i += 256) Ws[i] = W[i];
    size_t row0 = (size_t)blockIdx.x * 32;
    const float* xrow = x + row0 * 256;
    for (int i = tid; i < 32 * 256; i += 256) xs[i] = xrow[i];
    __syncthreads();

    int j = tid & 63;
    int rg = tid >> 6;            // 0..3
    float acc[8];
#pragma unroll
    for (int s = 0; s < 8; s++) acc[s] = 0.0f;

    const float4* xs4 = (const float4*)xs;
    for (int k4 = 0; k4 < 64; k4++) {
        float w0 = Ws[(4 * k4 + 0) * 64 + j];
        float w1 = Ws[(4 * k4 + 1) * 64 + j];
        float w2 = Ws[(4 * k4 + 2) * 64 + j];
        float w3 = Ws[(4 * k4 + 3) * 64 + j];
#pragma unroll
        for (int s = 0; s < 8; s++) {
            float4 xv = xs4[(rg * 8 + s) * 64 + k4];
            acc[s] += xv.x * w0 + xv.y * w1 + xv.z * w2 + xv.w * w3;
        }
    }
    float bb = b[j];
#pragma unroll
    for (int s = 0; s < 8; s++) {
        size_t r = row0 + rg * 8 + s;
        g_h[r * 64 + j] = gelu_exact(acc[s] + bb);
    }
}

// ============================================================
// qkv: g_q/g_k/g_v = g_h @ {Wq,Wk,Wv}   [100000,64]x[64,64] x3
// ============================================================
__global__ void qkv_kernel(const float* __restrict__ Wq,
                           const float* __restrict__ Wk,
                           const float* __restrict__ Wv) {
    extern __shared__ float sm[];
    float* Ws = sm;               // [k][c], 64*192
    float* hs = sm + 64 * 192;    // [r][k], 16*64
    int tid = threadIdx.x;        // 0..191

    for (int i = tid; i < 64 * 64; i += 192) {
        int k = i >> 6, c = i & 63;
        Ws[k * 192 + c]       = Wq[i];
        Ws[k * 192 + 64 + c]  = Wk[i];
        Ws[k * 192 + 128 + c] = Wv[i];
    }
    size_t row0 = (size_t)blockIdx.x * 16;
    for (int i = tid; i < 16 * 64; i += 192) hs[i] = g_h[row0 * 64 + i];
    __syncthreads();

    int c = tid;
    float acc[16];
#pragma unroll
    for (int r = 0; r < 16; r++) acc[r] = 0.0f;

    const float4* hs4 = (const float4*)hs;
    for (int k4 = 0; k4 < 16; k4++) {
        float w0 = Ws[(4 * k4 + 0) * 192 + c];
        float w1 = Ws[(4 * k4 + 1) * 192 + c];
        float w2 = Ws[(4 * k4 + 2) * 192 + c];
        float w3 = Ws[(4 * k4 + 3) * 192 + c];
#pragma unroll
        for (int r = 0; r < 16; r++) {
            float4 hv = hs4[r * 16 + k4];
            acc[r] += hv.x * w0 + hv.y * w1 + hv.z * w2 + hv.w * w3;
        }
    }
    float* outp;
    int cc;
    if (c < 64)       { outp = g_q; cc = c; }
    else if (c < 128) { outp = g_k; cc = c - 64; }
    else              { outp = g_v; cc = c - 128; }
#pragma unroll
    for (int r = 0; r < 16; r++) outp[(row0 + r) * 64 + cc] = acc[r];
}

// ============================================================
// CSR build: histogram -> scan -> fill
// ============================================================
__global__ void hist_zero_kernel() {
    int i = blockIdx.x * blockDim.x + threadIdx.x;
    if (i < Nn) g_cnt[i] = 0;
}
__global__ void hist_kernel(const int* __restrict__ dst) {
    int i = blockIdx.x * blockDim.x + threadIdx.x;
    if (i < Ee) atomicAdd(&g_cnt[__ldg(dst + i)], 1);
}

__global__ void scanA_kernel() {
    __shared__ int wsum[32];
    int i = blockIdx.x * 1024 + threadIdx.x;
    int lane = threadIdx.x & 31, wid = threadIdx.x >> 5;
    int v = (i < Nn) ? g_cnt[i] : 0;
    int x = v;
#pragma unroll
    for (int o = 1; o < 32; o <<= 1) {
        int t = __shfl_up_sync(0xFFFFFFFFu, x, o);
        if (lane >= o) x += t;
    }
    if (lane == 31) wsum[wid] = x;
    __syncthreads();
    if (wid == 0) {
        int y = wsum[lane];
#pragma unroll
        for (int o = 1; o < 32; o <<= 1) {
            int t = __shfl_up_sync(0xFFFFFFFFu, y, o);
            if (lane >= o) y += t;
        }
        wsum[lane] = y;
    }
    __syncthreads();
    int excl = x - v + (wid ? wsum[wid - 1] : 0);
    if (i < Nn) g_off[i] = excl;
    if (threadIdx.x == 1023) g_bsum[blockIdx.x] = excl + v;
}

__global__ void scanB_kernel() {
    __shared__ int sm[128];
    int t = threadIdx.x;
    int v = (t < NB_SCAN) ? g_bsum[t] : 0;
    sm[t] = v;
    __syncthreads();
#pragma unroll
    for (int o = 1; o < 128; o <<= 1) {
        int add = (t >= o) ? sm[t - o] : 0;
        __syncthreads();
        sm[t] += add;
        __syncthreads();
    }
    if (t < NB_SCAN) g_bpre[t] = sm[t] - v;  // exclusive
}

__global__ void scanC_kernel() {
    int i = blockIdx.x * 1024 + threadIdx.x;
    if (i < Nn) {
        int o = g_off[i] + g_bpre[blockIdx.x];
        g_off[i] = o;
        g_cur[i] = o;
    }
}

__global__ void fill_kernel(const int* __restrict__ src,
                            const int* __restrict__ dst) {
    int i = blockIdx.x * blockDim.x + threadIdx.x;
    if (i >= Ee) return;
    int d = __ldg(dst + i);
    int pos = atomicAdd(&g_cur[d], 1);
    g_csrc[pos] = __ldg(src + i);
    g_ceid[pos] = i;
}

// ============================================================
// fused GAT layer: warp per destination node.
// phase1: scores + segment max; phase2: exp + denom; phase3: gather-aggregate.
// LAYER==0: writes gelu(out) to g_h. LAYER==1: writes signals = out@Wsig + b.
// ============================================================
template <int LAYER>
__global__ void gat_kernel(const float* __restrict__ Wsig,
                           const float* __restrict__ bsig,
                           float* __restrict__ attn_out,
                           float* __restrict__ signals) {
    int w = (blockIdx.x * blockDim.x + threadIdx.x) >> 5;
    int lane = threadIdx.x & 31;
    if (w >= Nn) return;
    int start = g_off[w];
    int deg = g_cnt[w];

    float q0 = g_q[(size_t)w * 64 + lane];
    float q1 = g_q[(size_t)w * 64 + lane + 32];

    // ---- phase 1: scores (warp-cooperative dot per edge) + max ----
    float m = 0.0f;
    for (int i = 0; i < deg; i++) {
        int s = g_csrc[start + i];
        const float* kp = g_k + (size_t)s * 64;
        float p = q0 * kp[lane] + q1 * kp[lane + 32];
#pragma unroll
        for (int o = 16; o; o >>= 1) p += __shfl_xor_sync(0xFFFFFFFFu, p, o);
        float a = fmaxf(p * 0.125f, 0.0f);   // /sqrt(64), relu
        if (lane == (i & 31)) g_e[start + i] = a;
        m = fmaxf(m, a);                      // same on all lanes
    }
    __syncwarp();

    // ---- phase 2: exp + denom ----
    float sum = 0.0f;
    for (int i = lane; i < deg; i += 32) {
        float e = expf(g_e[start + i] - m);
        g_e[start + i] = e;
        sum += e;
    }
#pragma unroll
    for (int o = 16; o; o >>= 1) sum += __shfl_xor_sync(0xFFFFFFFFu, sum, o);
    float inv = 1.0f / (sum + 1e-16f);
    __syncwarp();

    // ---- phase 3: weighted gather of v ----
    float acc0 = 0.0f, acc1 = 0.0f;
    for (int i = 0; i < deg; i++) {
        int s = g_csrc[start + i];
        float a = g_e[start + i] * inv;       // broadcast load
        if (lane == (i & 31)) attn_out[g_ceid[start + i]] = a;
        const float* vp = g_v + (size_t)s * 64;
        acc0 += a * vp[lane];
        acc1 += a * vp[lane + 32];
    }

    if (LAYER == 0) {
        g_h[(size_t)w * 64 + lane]      = gelu_exact(acc0);
        g_h[(size_t)w * 64 + lane + 32] = gelu_exact(acc1);
    } else {
        float p = acc0 * __ldg(Wsig + lane) + acc1 * __ldg(Wsig + lane + 32);
#pragma unroll
        for (int o = 16; o; o >>= 1) p += __shfl_xor_sync(0xFFFFFFFFu, p, o);
        if (lane == 0) signals[w] = p + __ldg(bsig);
    }
}

// ============================================================
// host launcher
// ============================================================
extern "C" void kernel_launch(void* const* d_in, const int* in_sizes, int n_in,
                              void* d_out, int out_size) {
    const float* x    = (const float*)d_in[0];
    const int*   ei   = (const int*)d_in[1];
    const int*   src  = ei;          // edge_index[0]
    const int*   dst  = ei + Ee;     // edge_index[1]
    const float* Wp   = (const float*)d_in[2];
    const float* bp   = (const float*)d_in[3];
    const float* Wq1  = (const float*)d_in[4];
    const float* Wk1  = (const float*)d_in[5];
    const float* Wv1  = (const float*)d_in[6];
    const float* Wq2  = (const float*)d_in[7];
    const float* Wk2  = (const float*)d_in[8];
    const float* Wv2  = (const float*)d_in[9];
    const float* Wsig = (const float*)d_in[10];
    const float* bsig = (const float*)d_in[11];

    float* out     = (float*)d_out;
    float* signals = out;            // [Nn]
    float* attn1   = out + Nn;       // [Ee]
    float* attn2   = out + Nn + Ee;  // [Ee]

    const int PROJ_SMEM = (256 * 64 + 32 * 256) * 4;   // 96 KB
    const int QKV_SMEM  = (64 * 192 + 16 * 64) * 4;    // 52 KB
    cudaFuncSetAttribute(proj_kernel, cudaFuncAttributeMaxDynamicSharedMemorySize, PROJ_SMEM);
    cudaFuncSetAttribute(qkv_kernel,  cudaFuncAttributeMaxDynamicSharedMemorySize, QKV_SMEM);

    // ---- proj + gelu ----
    proj_kernel<<<Nn / 32, 256, PROJ_SMEM>>>(x, Wp, bp);

    // ---- CSR build (shared by both layers) ----
    hist_zero_kernel<<<(Nn + 255) / 256, 256>>>();
    hist_kernel<<<(Ee + 255) / 256, 256>>>(dst);
    scanA_kernel<<<NB_SCAN, 1024>>>();
    scanB_kernel<<<1, 128>>>();
    scanC_kernel<<<NB_SCAN, 1024>>>();
    fill_kernel<<<(Ee + 255) / 256, 256>>>(src, dst);

    // ---- layer 1 ----
    qkv_kernel<<<Nn / 16, 192, QKV_SMEM>>>(Wq1, Wk1, Wv1);
    gat_kernel<0><<<(Nn + 7) / 8, 256>>>(Wsig, bsig, attn1, signals);

    // ---- layer 2 ----
    qkv_kernel<<<Nn / 16, 192, QKV_SMEM>>>(Wq2, Wk2, Wv2);
    gat_kernel<1><<<(Nn + 7) / 8, 256>>>(Wsig, bsig, attn2, signals);
}

// round 4
// speedup vs baseline: 2.3977x; 1.4458x over previous
#include <cuda_runtime.h>
#include <math.h>

#define Nn 100000
#define Ee 1600000
#define Ff 256
#define Hh 64
#define NB_SCAN 98   // ceil(Nn/1024)

// ---- device scratch (static: no allocation allowed) ----
__device__ float g_h[(size_t)Nn * Hh];   // node features (layer input)
__device__ float g_q[(size_t)Nn * Hh];
__device__ float g_k[(size_t)Nn * Hh];
__device__ float g_v[(size_t)Nn * Hh];
__device__ float g_e[(size_t)Ee];        // per-edge alpha, then exp(alpha-m)
__device__ int   g_cnt[Nn];              // per-dst degree
__device__ int   g_off[Nn];              // CSR exclusive offsets
__device__ int   g_cur[Nn];              // fill cursors
__device__ int   g_csrc[Ee];             // CSR: source node per slot
__device__ int   g_ceid[Ee];             // CSR: original edge id per slot
__device__ int   g_bsum[128];
__device__ int   g_bpre[128];

__device__ __forceinline__ float gelu_exact(float v) {
    return 0.5f * v * (1.0f + erff(v * 0.70710678118654752440f));
}

__device__ __forceinline__ unsigned f2tf32(float v) {
    unsigned r;
    asm("cvt.rna.tf32.f32 %0, %1;" : "=r"(r) : "f"(v));
    return r;
}

__device__ __forceinline__ void mma_tf32(float& c0, float& c1, float& c2, float& c3,
                                         unsigned a0, unsigned a1, unsigned a2, unsigned a3,
                                         unsigned b0, unsigned b1) {
    asm volatile(
        "mma.sync.aligned.m16n8k8.row.col.f32.tf32.tf32.f32 "
        "{%0,%1,%2,%3},{%4,%5,%6,%7},{%8,%9},{%0,%1,%2,%3};"
        : "+f"(c0), "+f"(c1), "+f"(c2), "+f"(c3)
        : "r"(a0), "r"(a1), "r"(a2), "r"(a3), "r"(b0), "r"(b1));
}

// ============================================================
// proj (tensor core): g_h = gelu(x @ W_proj + b)  [100000,256]x[256,64]
// block: 256 thr (8 warps), tile 128 rows x 64 cols; K staged in 32-chunks.
// As[m][k]: stride 36 -> frag loads conflict-free (bank = lane).
// Bs[n][k]: full W transposed, stride 260 (≡4 mod 32) -> conflict-free.
// ============================================================
#define PROJ_SMEM_U ((128 * 36 + 64 * 260) * 4)
__global__ void proj_mma_kernel(const float* __restrict__ x,
                                const float* __restrict__ W,
                                const float* __restrict__ b) {
    extern __shared__ unsigned sm[];
    unsigned* As = sm;             // 128*36
    unsigned* Bs = sm + 128 * 36;  // 64*260
    int tid = threadIdx.x;
    int w = tid >> 5, lane = tid & 31;
    int g = lane >> 2, c = lane & 3;
    size_t row0 = (size_t)blockIdx.x * 128;

    // load full W transposed: Bs[n*260 + k] = tf32(W[k*64+n])
    for (int i = tid; i < 256 * 64; i += 256) {
        int k = i >> 6, n = i & 63;
        Bs[n * 260 + k] = f2tf32(W[i]);
    }

    float acc[8][4];
#pragma unroll
    for (int nt = 0; nt < 8; nt++)
#pragma unroll
        for (int e = 0; e < 4; e++) acc[nt][e] = 0.0f;

    const float4* x4 = (const float4*)x;
    for (int k0 = 0; k0 < 256; k0 += 32) {
        __syncthreads();   // prev iter's frag reads done
        // stage A tile: 128 rows x 32 k
#pragma unroll
        for (int j = 0; j < 4; j++) {
            int f = tid + 256 * j;          // 0..1023
            int r = f >> 3, c8 = f & 7;     // row, float4-chunk
            size_t rr = row0 + r; if (rr >= Nn) rr = Nn - 1;
            float4 v = x4[rr * 64 + (k0 >> 2) + c8];
            unsigned* p = As + r * 36 + c8 * 4;
            p[0] = f2tf32(v.x); p[1] = f2tf32(v.y);
            p[2] = f2tf32(v.z); p[3] = f2tf32(v.w);
        }
        __syncthreads();

#pragma unroll
        for (int ks = 0; ks < 4; ks++) {
            int kk = ks * 8;
            const unsigned* ap = As + (w * 16 + g) * 36 + kk + c;
            unsigned a0 = ap[0], a1 = ap[8 * 36], a2 = ap[4], a3 = ap[8 * 36 + 4];
#pragma unroll
            for (int nt = 0; nt < 8; nt++) {
                const unsigned* bp = Bs + (nt * 8 + g) * 260 + k0 + kk + c;
                mma_tf32(acc[nt][0], acc[nt][1], acc[nt][2], acc[nt][3],
                         a0, a1, a2, a3, bp[0], bp[4]);
            }
        }
    }

    // epilogue: bias + gelu
    size_t r0 = row0 + w * 16 + g;
    size_t r1 = r0 + 8;
#pragma unroll
    for (int nt = 0; nt < 8; nt++) {
        int col = nt * 8 + c * 2;
        float b0 = __ldg(b + col), b1 = __ldg(b + col + 1);
        if (r0 < Nn) {
            g_h[r0 * 64 + col]     = gelu_exact(acc[nt][0] + b0);
            g_h[r0 * 64 + col + 1] = gelu_exact(acc[nt][1] + b1);
        }
        if (r1 < Nn) {
            g_h[r1 * 64 + col]     = gelu_exact(acc[nt][2] + b0);
            g_h[r1 * 64 + col + 1] = gelu_exact(acc[nt][3] + b1);
        }
    }
}

// ============================================================
// qkv (tensor core): g_q/g_k/g_v = g_h @ {Wq,Wk,Wv}  [100000,64]x[64,192]
// block: 256 thr, tile 128 rows x 192 cols, K=64 loaded once.
// As[m][k] stride 68, Bs[n][k] stride 68 (both ≡4 mod 32 -> conflict-free).
// ============================================================
#define QKV_SMEM_U ((128 * 68 + 192 * 68) * 4)
__global__ void qkv_mma_kernel(const float* __restrict__ Wq,
                               const float* __restrict__ Wk,
                               const float* __restrict__ Wv) {
    extern __shared__ unsigned sm[];
    unsigned* As = sm;             // 128*68
    unsigned* Bs = sm + 128 * 68;  // 192*68
    int tid = threadIdx.x;
    int w = tid >> 5, lane = tid & 31;
    int g = lane >> 2, c = lane & 3;
    size_t row0 = (size_t)blockIdx.x * 128;

    // load Wq|Wk|Wv transposed: Bs[(off+n)*68 + k]
    for (int i = tid; i < 64 * 64; i += 256) {
        int k = i >> 6, n = i & 63;
        Bs[n * 68 + k]         = f2tf32(Wq[i]);
        Bs[(64 + n) * 68 + k]  = f2tf32(Wk[i]);
        Bs[(128 + n) * 68 + k] = f2tf32(Wv[i]);
    }
    // stage A: 128 rows x 64 k
    const float4* h4 = (const float4*)g_h;
#pragma unroll
    for (int j = 0; j < 8; j++) {
        int f = tid + 256 * j;           // 0..2047
        int r = f >> 4, c16 = f & 15;
        size_t rr = row0 + r; if (rr >= Nn) rr = Nn - 1;
        float4 v = h4[rr * 16 + c16];
        unsigned* p = As + r * 68 + c16 * 4;
        p[0] = f2tf32(v.x); p[1] = f2tf32(v.y);
        p[2] = f2tf32(v.z); p[3] = f2tf32(v.w);
    }
    __syncthreads();

    float acc[24][4];
#pragma unroll
    for (int nt = 0; nt < 24; nt++)
#pragma unroll
        for (int e = 0; e < 4; e++) acc[nt][e] = 0.0f;

#pragma unroll
    for (int ks = 0; ks < 8; ks++) {
        int kk = ks * 8;
        const unsigned* ap = As + (w * 16 + g) * 68 + kk + c;
        unsigned a0 = ap[0], a1 = ap[8 * 68], a2 = ap[4], a3 = ap[8 * 68 + 4];
#pragma unroll
        for (int nt = 0; nt < 24; nt++) {
            const unsigned* bp = Bs + (nt * 8 + g) * 68 + kk + c;
            mma_tf32(acc[nt][0], acc[nt][1], acc[nt][2], acc[nt][3],
                     a0, a1, a2, a3, bp[0], bp[4]);
        }
    }

    size_t r0 = row0 + w * 16 + g;
    size_t r1 = r0 + 8;
#pragma unroll
    for (int nt = 0; nt < 24; nt++) {
        int col = nt * 8 + c * 2;
        float* outp = (col < 64) ? g_q : (col < 128) ? g_k : g_v;
        int cc = col & 63;
        if (r0 < Nn) {
            outp[r0 * 64 + cc]     = acc[nt][0];
            outp[r0 * 64 + cc + 1] = acc[nt][1];
        }
        if (r1 < Nn) {
            outp[r1 * 64 + cc]     = acc[nt][2];
            outp[r1 * 64 + cc + 1] = acc[nt][3];
        }
    }
}

// ============================================================
// CSR build: histogram -> scan -> fill
// ============================================================
__global__ void hist_zero_kernel() {
    int i = blockIdx.x * blockDim.x + threadIdx.x;
    if (i < Nn) g_cnt[i] = 0;
}
__global__ void hist_kernel(const int* __restrict__ dst) {
    int i = blockIdx.x * blockDim.x + threadIdx.x;
    if (i < Ee) atomicAdd(&g_cnt[__ldg(dst + i)], 1);
}

__global__ void scanA_kernel() {
    __shared__ int wsum[32];
    int i = blockIdx.x * 1024 + threadIdx.x;
    int lane = threadIdx.x & 31, wid = threadIdx.x >> 5;
    int v = (i < Nn) ? g_cnt[i] : 0;
    int x = v;
#pragma unroll
    for (int o = 1; o < 32; o <<= 1) {
        int t = __shfl_up_sync(0xFFFFFFFFu, x, o);
        if (lane >= o) x += t;
    }
    if (lane == 31) wsum[wid] = x;
    __syncthreads();
    if (wid == 0) {
        int y = wsum[lane];
#pragma unroll
        for (int o = 1; o < 32; o <<= 1) {
            int t = __shfl_up_sync(0xFFFFFFFFu, y, o);
            if (lane >= o) y += t;
        }
        wsum[lane] = y;
    }
    __syncthreads();
    int excl = x - v + (wid ? wsum[wid - 1] : 0);
    if (i < Nn) g_off[i] = excl;
    if (threadIdx.x == 1023) g_bsum[blockIdx.x] = excl + v;
}

__global__ void scanB_kernel() {
    __shared__ int sm[128];
    int t = threadIdx.x;
    int v = (t < NB_SCAN) ? g_bsum[t] : 0;
    sm[t] = v;
    __syncthreads();
#pragma unroll
    for (int o = 1; o < 128; o <<= 1) {
        int add = (t >= o) ? sm[t - o] : 0;
        __syncthreads();
        sm[t] += add;
        __syncthreads();
    }
    if (t < NB_SCAN) g_bpre[t] = sm[t] - v;  // exclusive
}

__global__ void scanC_kernel() {
    int i = blockIdx.x * 1024 + threadIdx.x;
    if (i < Nn) {
        int o = g_off[i] + g_bpre[blockIdx.x];
        g_off[i] = o;
        g_cur[i] = o;
    }
}

__global__ void fill_kernel(const int* __restrict__ src,
                            const int* __restrict__ dst) {
    int i = blockIdx.x * blockDim.x + threadIdx.x;
    if (i >= Ee) return;
    int d = __ldg(dst + i);
    int pos = atomicAdd(&g_cur[d], 1);
    g_csrc[pos] = __ldg(src + i);
    g_ceid[pos] = i;
}

// ============================================================
// fused GAT layer: warp per destination node.
// ============================================================
template <int LAYER>
__global__ void gat_kernel(const float* __restrict__ Wsig,
                           const float* __restrict__ bsig,
                           float* __restrict__ attn_out,
                           float* __restrict__ signals) {
    int w = (blockIdx.x * blockDim.x + threadIdx.x) >> 5;
    int lane = threadIdx.x & 31;
    if (w >= Nn) return;
    int start = g_off[w];
    int deg = g_cnt[w];

    float q0 = g_q[(size_t)w * 64 + lane];
    float q1 = g_q[(size_t)w * 64 + lane + 32];

    // ---- phase 1: scores + max ----
    float m = 0.0f;
    for (int i = 0; i < deg; i++) {
        int s = g_csrc[start + i];
        const float* kp = g_k + (size_t)s * 64;
        float p = q0 * kp[lane] + q1 * kp[lane + 32];
#pragma unroll
        for (int o = 16; o; o >>= 1) p += __shfl_xor_sync(0xFFFFFFFFu, p, o);
        float a = fmaxf(p * 0.125f, 0.0f);
        if (lane == (i & 31)) g_e[start + i] = a;
        m = fmaxf(m, a);
    }
    __syncwarp();

    // ---- phase 2: exp + denom ----
    float sum = 0.0f;
    for (int i = lane; i < deg; i += 32) {
        float e = expf(g_e[start + i] - m);
        g_e[start + i] = e;
        sum += e;
    }
#pragma unroll
    for (int o = 16; o; o >>= 1) sum += __shfl_xor_sync(0xFFFFFFFFu, sum, o);
    float inv = 1.0f / (sum + 1e-16f);
    __syncwarp();

    // ---- phase 3: weighted gather of v ----
    float acc0 = 0.0f, acc1 = 0.0f;
    for (int i = 0; i < deg; i++) {
        int s = g_csrc[start + i];
        float a = g_e[start + i] * inv;
        if (lane == (i & 31)) attn_out[g_ceid[start + i]] = a;
        const float* vp = g_v + (size_t)s * 64;
        acc0 += a * vp[lane];
        acc1 += a * vp[lane + 32];
    }

    if (LAYER == 0) {
        g_h[(size_t)w * 64 + lane]      = gelu_exact(acc0);
        g_h[(size_t)w * 64 + lane + 32] = gelu_exact(acc1);
    } else {
        float p = acc0 * __ldg(Wsig + lane) + acc1 * __ldg(Wsig + lane + 32);
#pragma unroll
        for (int o = 16; o; o >>= 1) p += __shfl_xor_sync(0xFFFFFFFFu, p, o);
        if (lane == 0) signals[w] = p + __ldg(bsig);
    }
}

// ============================================================
// host launcher
// ============================================================
extern "C" void kernel_launch(void* const* d_in, const int* in_sizes, int n_in,
                              void* d_out, int out_size) {
    const float* x    = (const float*)d_in[0];
    const int*   ei   = (const int*)d_in[1];
    const int*   src  = ei;          // edge_index[0]
    const int*   dst  = ei + Ee;     // edge_index[1]
    const float* Wp   = (const float*)d_in[2];
    const float* bp   = (const float*)d_in[3];
    const float* Wq1  = (const float*)d_in[4];
    const float* Wk1  = (const float*)d_in[5];
    const float* Wv1  = (const float*)d_in[6];
    const float* Wq2  = (const float*)d_in[7];
    const float* Wk2  = (const float*)d_in[8];
    const float* Wv2  = (const float*)d_in[9];
    const float* Wsig = (const float*)d_in[10];
    const float* bsig = (const float*)d_in[11];

    float* out     = (float*)d_out;
    float* signals = out;            // [Nn]
    float* attn1   = out + Nn;       // [Ee]
    float* attn2   = out + Nn + Ee;  // [Ee]

    cudaFuncSetAttribute(proj_mma_kernel, cudaFuncAttributeMaxDynamicSharedMemorySize, PROJ_SMEM_U);
    cudaFuncSetAttribute(qkv_mma_kernel,  cudaFuncAttributeMaxDynamicSharedMemorySize, QKV_SMEM_U);

    const int MBLK = 128;
    const int nblk = (Nn + MBLK - 1) / MBLK;   // 782

    // ---- proj + gelu ----
    proj_mma_kernel<<<nblk, 256, PROJ_SMEM_U>>>(x, Wp, bp);

    // ---- CSR build (shared by both layers) ----
    hist_zero_kernel<<<(Nn + 255) / 256, 256>>>();
    hist_kernel<<<(Ee + 255) / 256, 256>>>(dst);
    scanA_kernel<<<NB_SCAN, 1024>>>();
    scanB_kernel<<<1, 128>>>();
    scanC_kernel<<<NB_SCAN, 1024>>>();
    fill_kernel<<<(Ee + 255) / 256, 256>>>(src, dst);

    // ---- layer 1 ----
    qkv_mma_kernel<<<nblk, 256, QKV_SMEM_U>>>(Wq1, Wk1, Wv1);
    gat_kernel<0><<<(Nn + 7) / 8, 256>>>(Wsig, bsig, attn1, signals);

    // ---- layer 2 ----
    qkv_mma_kernel<<<nblk, 256, QKV_SMEM_U>>>(Wq2, Wk2, Wv2);
    gat_kernel<1><<<(Nn + 7) / 8, 256>>>(Wsig, bsig, attn2, signals);
}